// round 2
// baseline (speedup 1.0000x reference)
#include <cuda_runtime.h>
#include <cuda_bf16.h>

// COO SpMM, rows sorted: out[r] = sum_{(r,c,v)} v * x[c].  N=100000, E=1.6M, D=48.
// Strategy: warp-per-row CSR. Per row: batch-load up to 32 (col,val) pairs with
// 2 lane-strided LDGs, then gather TWO x-rows per LDG.128 (lanes 0-11 edge k,
// lanes 12-23 edge k+1, float4 each), combine partials with one shuffle, store
// the 48-float output row with a single LDG.128-wide STG from 12 lanes.
// This minimizes LDG warp-instruction count (the measured bottleneck).

#define D_FEAT 48
#define WPB 8            // warps (rows) per block -> 256 threads
#define MAX_NODES 100000

__device__ int g_row_ptr[MAX_NODES + 1];

// Build CSR row pointers by binary search over sorted `rows`.
__global__ void build_row_ptr_kernel(const int* __restrict__ rows, int E, int N) {
    int r = blockIdx.x * blockDim.x + threadIdx.x;
    if (r > N) return;
    if (r == N) { g_row_ptr[N] = E; return; }
    int lo = 0, hi = E;
    while (lo < hi) {
        int mid = (lo + hi) >> 1;
        if (__ldg(&rows[mid]) < r) lo = mid + 1;
        else hi = mid;
    }
    g_row_ptr[r] = lo;
}

__global__ void __launch_bounds__(32 * WPB)
spmm_warp_kernel(const float* __restrict__ x,
                 const int* __restrict__ cols,
                 const float* __restrict__ vals,
                 float* __restrict__ out,
                 int N) {
    const int warp_id = threadIdx.x >> 5;
    const int lane    = threadIdx.x & 31;
    const int row     = blockIdx.x * WPB + warp_id;
    if (row >= N) return;

    const int e0 = g_row_ptr[row];
    const int e1 = g_row_ptr[row + 1];

    const int sub = lane / 12;   // 0 or 1 for active gather lanes; 2 = idle
    const int fl  = lane % 12;   // float4 slot within the 48-float row
    const unsigned FULL = 0xffffffffu;

    float4 acc = make_float4(0.f, 0.f, 0.f, 0.f);

    for (int base = e0; base < e1; base += 32) {
        const int n = min(32, e1 - base);
        int   c = 0;
        float v = 0.f;
        if (lane < n) {
            c = __ldg(&cols[base + lane]);
            v = __ldg(&vals[base + lane]);
        }
        for (int k = 0; k < n; k += 2) {
            const int   idx = k + sub;
            const int   myc = __shfl_sync(FULL, c, idx & 31);
            const float myv = __shfl_sync(FULL, v, idx & 31);
            if (sub < 2 && idx < n) {
                const float4* __restrict__ xr =
                    (const float4*)(x + (size_t)myc * D_FEAT);
                float4 b = __ldg(&xr[fl]);
                acc.x += myv * b.x;
                acc.y += myv * b.y;
                acc.z += myv * b.z;
                acc.w += myv * b.w;
            }
        }
    }

    // Fold lane 12+fl partials into lane fl.
    const int src = (lane + 12) & 31;
    float ox = __shfl_sync(FULL, acc.x, src);
    float oy = __shfl_sync(FULL, acc.y, src);
    float oz = __shfl_sync(FULL, acc.z, src);
    float ow = __shfl_sync(FULL, acc.w, src);

    if (lane < 12) {
        float4 r;
        r.x = acc.x + ox;
        r.y = acc.y + oy;
        r.z = acc.z + oz;
        r.w = acc.w + ow;
        ((float4*)(out + (size_t)row * D_FEAT))[fl] = r;
    }
}

extern "C" void kernel_launch(void* const* d_in, const int* in_sizes, int n_in,
                              void* d_out, int out_size) {
    // metadata order: t, x, rows, cols, vals
    const float* x    = (const float*)d_in[1];
    const int*   rows = (const int*)d_in[2];
    const int*   cols = (const int*)d_in[3];
    const float* vals = (const float*)d_in[4];
    float*       out  = (float*)d_out;

    const int E = in_sizes[2];
    const int N = out_size / D_FEAT;

    {
        int threads = 256;
        int blocks  = (N + 1 + threads) / threads;
        build_row_ptr_kernel<<<blocks, threads>>>(rows, E, N);
    }
    {
        int grid = (N + WPB - 1) / WPB;
        spmm_warp_kernel<<<grid, 32 * WPB>>>(x, cols, vals, out, N);
    }
}

// round 3
// speedup vs baseline: 1.2250x; 1.2250x over previous
#include <cuda_runtime.h>
#include <cuda_bf16.h>

// COO SpMM, rows sorted: out[r] = sum_{(r,c,v)} v * x[c].  N=100000, E=1.6M, D=48.
// R3: R1 structure (row-parallel CSR, no atomics, no shuffles) but the gather is
// a single LDG.128 per edge: 12 lanes per row each own one float4 of the 48-float
// x row. Cuts LDG-instruction count and L1 wavefronts ~1.5x vs R1 (the measured
// binding resources). Metadata loads are uniform within a 12-lane group.

#define D_FEAT   48
#define D_VEC    12          // 48 floats = 12 float4
#define TPR      12          // threads per row (one float4 each)
#define RPB      16          // rows per block -> 192 threads
#define MAX_NODES 100000

__device__ int g_row_ptr[MAX_NODES + 1];

// Build CSR row pointers by binary search over sorted `rows`.
__global__ void build_row_ptr_kernel(const int* __restrict__ rows, int E, int N) {
    int r = blockIdx.x * blockDim.x + threadIdx.x;
    if (r > N) return;
    if (r == N) { g_row_ptr[N] = E; return; }
    int lo = 0, hi = E;
    while (lo < hi) {
        int mid = (lo + hi) >> 1;
        if (__ldg(&rows[mid]) < r) lo = mid + 1;
        else hi = mid;
    }
    g_row_ptr[r] = lo;
}

__global__ void __launch_bounds__(TPR * RPB)
spmm_csr_vec_kernel(const float4* __restrict__ x4,
                    const int*    __restrict__ cols,
                    const float*  __restrict__ vals,
                    float4*       __restrict__ out4,
                    int N) {
    const int row = blockIdx.x * RPB + threadIdx.y;
    if (row >= N) return;
    const int fl = threadIdx.x;              // 0..11: float4 slot in the row

    int e   = g_row_ptr[row];
    const int end = g_row_ptr[row + 1];

    float4 acc = make_float4(0.f, 0.f, 0.f, 0.f);

    // Unroll by 2 for memory-level parallelism.
    for (; e + 1 < end; e += 2) {
        const int   c0 = __ldg(&cols[e]);
        const int   c1 = __ldg(&cols[e + 1]);
        const float v0 = __ldg(&vals[e]);
        const float v1 = __ldg(&vals[e + 1]);
        const float4 b0 = __ldg(&x4[(size_t)c0 * D_VEC + fl]);
        const float4 b1 = __ldg(&x4[(size_t)c1 * D_VEC + fl]);
        acc.x = fmaf(v0, b0.x, acc.x);
        acc.y = fmaf(v0, b0.y, acc.y);
        acc.z = fmaf(v0, b0.z, acc.z);
        acc.w = fmaf(v0, b0.w, acc.w);
        acc.x = fmaf(v1, b1.x, acc.x);
        acc.y = fmaf(v1, b1.y, acc.y);
        acc.z = fmaf(v1, b1.z, acc.z);
        acc.w = fmaf(v1, b1.w, acc.w);
    }
    if (e < end) {
        const int   c = __ldg(&cols[e]);
        const float v = __ldg(&vals[e]);
        const float4 b = __ldg(&x4[(size_t)c * D_VEC + fl]);
        acc.x = fmaf(v, b.x, acc.x);
        acc.y = fmaf(v, b.y, acc.y);
        acc.z = fmaf(v, b.z, acc.z);
        acc.w = fmaf(v, b.w, acc.w);
    }

    out4[(size_t)row * D_VEC + fl] = acc;
}

extern "C" void kernel_launch(void* const* d_in, const int* in_sizes, int n_in,
                              void* d_out, int out_size) {
    // metadata order: t, x, rows, cols, vals
    const float* x    = (const float*)d_in[1];
    const int*   rows = (const int*)d_in[2];
    const int*   cols = (const int*)d_in[3];
    const float* vals = (const float*)d_in[4];
    float*       out  = (float*)d_out;

    const int E = in_sizes[2];
    const int N = out_size / D_FEAT;

    {
        int threads = 256;
        int blocks  = (N + 1 + threads) / threads;
        build_row_ptr_kernel<<<blocks, threads>>>(rows, E, N);
    }
    {
        dim3 block(TPR, RPB);
        int  grid = (N + RPB - 1) / RPB;
        spmm_csr_vec_kernel<<<grid, block>>>((const float4*)x, cols, vals,
                                             (float4*)out, N);
    }
}